// round 17
// baseline (speedup 1.0000x reference)
#include <cuda_runtime.h>
#include <cuda_fp16.h>
#include <cstdint>
#include <math.h>

#define NQ    2048
#define DIM   256
#define NF    100000
#define NCLS  1000
#define KSEL  16
#define TAUF  0.2f
#define LSCALE 20.0f

#define BM 128
#define BN 128
#define NSTRIPE 37
#define TBASE 21             // tiles per stripe (first 5 stripes get +1)
#define KP 8                 // per (row, col-quarter) candidates per stripe
#define NCAND (NSTRIPE*4*KP) // 1184
#define CSEL 48

#define NT 512               // threads per CTA (16 warps), 1 CTA/SM

// smem layout (bytes, dynamic)
#define SM_A   0                 // 128 x 256 fp16 blocked+swizzled : 65536
#define SM_B   65536             // 2 x full B tile (128 x 256 fp16): 131072
#define SM_S   196608            // 1 x (128 x 136 fp16) sims       : 34816
#define SROW   272
#define SM_TOTAL 231424          // 226 KB

// ---------------- device scratch ----------------
__device__ __half g_xb[NQ*DIM];
__device__ float  g_xn[NQ*DIM];
__device__ __half g_mb[(size_t)NF*DIM];
__device__ float  g_cval[(size_t)NQ*NCAND];
__device__ int    g_cidx[(size_t)NQ*NCAND];

// ---------------- PTX helpers ----------------
__device__ __forceinline__ void cpa16(unsigned dst, const void* src, int sz){
  asm volatile("cp.async.cg.shared.global [%0], [%1], 16, %2;\n"
    :: "r"(dst), "l"(__cvta_generic_to_global(src)), "r"(sz));
}
__device__ __forceinline__ void cpa_commit(){ asm volatile("cp.async.commit_group;\n"); }
template<int N> __device__ __forceinline__ void cpa_wait(){
  asm volatile("cp.async.wait_group %0;\n" :: "n"(N));
}
__device__ __forceinline__ void ldsm4(uint32_t* r, unsigned addr){
  asm volatile("ldmatrix.sync.aligned.m8n8.x4.shared.b16 {%0,%1,%2,%3}, [%4];\n"
    : "=r"(r[0]), "=r"(r[1]), "=r"(r[2]), "=r"(r[3]) : "r"(addr));
}
// fp16-accumulate HMMA: D(2 regs = 4 halves) = A*B + D
__device__ __forceinline__ void mma16816h(uint32_t* d, const uint32_t* a, uint32_t b0, uint32_t b1){
  asm volatile(
    "mma.sync.aligned.m16n8k16.row.col.f16.f16.f16.f16 "
    "{%0,%1}, {%2,%3,%4,%5}, {%6,%7}, {%0,%1};\n"
    : "+r"(d[0]), "+r"(d[1])
    : "r"(a[0]), "r"(a[1]), "r"(a[2]), "r"(a[3]), "r"(b0), "r"(b1));
}

// ---------------- kernel 1: setup (fp16 convert + standardize/normalize) ----------------
__global__ void setup_kernel(const float* __restrict__ x, const float* __restrict__ mean,
                             const float* __restrict__ stdv, const float* __restrict__ mf){
  {
    int stride = gridDim.x * blockDim.x;
    int n4 = NF*DIM/4;
    for (int i = blockIdx.x*blockDim.x + threadIdx.x; i < n4; i += stride){
      float4 f = ((const float4*)mf)[i];
      __half2* o = (__half2*)g_mb;
      o[2*i]   = __floats2half2_rn(f.x, f.y);
      o[2*i+1] = __floats2half2_rn(f.z, f.w);
    }
  }
  int r = blockIdx.x, t = threadIdx.x;
  float v = (x[r*DIM + t] - mean[t]) / stdv[t];
  float s = v*v;
  #pragma unroll
  for (int o = 16; o; o >>= 1) s += __shfl_xor_sync(0xffffffffu, s, o);
  __shared__ float ws[8];
  __shared__ float nrm;
  if ((t & 31) == 0) ws[t >> 5] = s;
  __syncthreads();
  if (t == 0){
    float tot = 0.f;
    #pragma unroll
    for (int i = 0; i < 8; i++) tot += ws[i];
    nrm = fmaxf(sqrtf(tot), 1e-6f);
  }
  __syncthreads();
  float o = v / nrm;
  g_xn[r*DIM + t] = o;
  g_xb[r*DIM + t] = __float2half_rn(o);
}

// ---------------- kernel 2: fp16 GEMM + top-k, whole-tile B ----------------
__device__ __forceinline__ void load_B_tile(unsigned sBu, int buf, int nb, int t){
  unsigned bbase = sBu + (unsigned)buf * 65536u;
  #pragma unroll
  for (int j = 0; j < 8; j++){
    int id = t + NT*j;             // 0..4095
    int q = id >> 10;              // 64-k chunk 0..3
    int r = (id >> 3) & 127;       // feature row
    int c = id & 7;                // 16B col within chunk
    int fr = nb + r;
    int ok = (fr < NF);
    cpa16(bbase + (unsigned)(q*16384 + (r*8 + ((c ^ r) & 7)) * 16),
          g_mb + (size_t)(ok ? fr : 0) * DIM + q*64 + c*8, ok ? 16 : 0);
  }
}

__global__ void __launch_bounds__(NT, 1) gemm_topk_kernel(){
  extern __shared__ char smem[];
  const unsigned sA_u = (unsigned)__cvta_generic_to_shared(smem);
  const unsigned sBu  = sA_u + SM_B;

  int t = threadIdx.x, lane = t & 31, w = t >> 5;
  int m0 = blockIdx.x * BM;
  int y  = blockIdx.y;
  int t0 = y * TBASE + min(y, 5);
  int ntiles = TBASE + (y < 5 ? 1 : 0);

  // scan identity: 4 threads per row, 32 cols each
  int srow = t & 127;
  int squad = t >> 7;

  float tv[KP]; int ti[KP];
  #pragma unroll
  for (int i = 0; i < KP; i++){ tv[i] = -INFINITY; ti[i] = 0; }
  float tmin = -INFINITY; int minpos = 0;

  // scan one 8-col chunk (one uint4 of fp16 sims) with hmax2 fast-reject
  auto scan_chunk = [&](int nb, int q){
    uint4 d = *(const uint4*)(smem + SM_S + srow*SROW + squad*64 + q*16);
    __half2 v0 = *(__half2*)&d.x;
    __half2 v1 = *(__half2*)&d.y;
    __half2 v2 = *(__half2*)&d.z;
    __half2 v3 = *(__half2*)&d.w;
    __half2 mm = __hmax2(__hmax2(v0, v1), __hmax2(v2, v3));
    float mx = __half2float(__hmax(mm.x, mm.y));
    if (mx > tmin){
      uint32_t word[4] = {d.x, d.y, d.z, d.w};
      int cbase = nb + squad*32 + q*8;
      #pragma unroll
      for (int h = 0; h < 4; h++){
        float2 f = __half22float2(*(__half2*)&word[h]);
        int gc0 = cbase + 2*h;
        if (f.x > tmin && gc0 < NF){
          #pragma unroll
          for (int qq = 0; qq < KP; qq++) if (qq == minpos){ tv[qq] = f.x; ti[qq] = gc0; }
          tmin = tv[0]; minpos = 0;
          #pragma unroll
          for (int qq = 1; qq < KP; qq++) if (tv[qq] < tmin){ tmin = tv[qq]; minpos = qq; }
        }
        if (f.y > tmin && gc0 + 1 < NF){
          #pragma unroll
          for (int qq = 0; qq < KP; qq++) if (qq == minpos){ tv[qq] = f.y; ti[qq] = gc0 + 1; }
          tmin = tv[0]; minpos = 0;
          #pragma unroll
          for (int qq = 1; qq < KP; qq++) if (tv[qq] < tmin){ tmin = tv[qq]; minpos = qq; }
        }
      }
    }
  };

  // prologue: A tile + B tile0 (group 0), B tile1 (group 1)
  #pragma unroll
  for (int j = 0; j < 8; j++){
    int id = t + NT*j;
    int row = id >> 5, c = id & 31;
    int phys = (c & 24) | ((c ^ row) & 7);
    cpa16(sA_u + (unsigned)((row*32 + phys)*16),
          g_xb + (size_t)(m0 + row)*DIM + c*8, 16);
  }
  load_B_tile(sBu, 0, (t0 + 0)*BN, t);
  cpa_commit();
  if (ntiles > 1) load_B_tile(sBu, 1, (t0 + 1)*BN, t);
  cpa_commit();

  int wr = (w >> 2) * 32;     // warp rows [wr, wr+32)
  int wc = (w & 3) * 32;      // warp cols [wc, wc+32)
  int hi = lane >> 4;
  int lo15 = lane & 15;

  // precompute B smem offsets: boff[ss][p] (within a 64-k chunk)
  unsigned boff[4][2];
  #pragma unroll
  for (int ss = 0; ss < 4; ss++){
    #pragma unroll
    for (int p = 0; p < 2; p++){
      int row = wc + 16*p + lo15;
      int c = 2*ss + hi;
      int phys = (c ^ row) & 7;
      boff[ss][p] = (unsigned)((row*8 + phys)*16);
    }
  }
  unsigned arow[2];
  #pragma unroll
  for (int mf = 0; mf < 2; mf++) arow[mf] = (unsigned)(wr + 16*mf + lo15);

  // fragment loader for flat step (q = step>>2, ss = step&3)
  auto frag_load = [&](int step, uint32_t af[2][4], uint32_t bv[2][4], unsigned tb){
    int q = step >> 2, ss = step & 3;
    int c = q*8 + 2*ss + hi;
    #pragma unroll
    for (int mf = 0; mf < 2; mf++){
      int row = arow[mf];
      int phys = (c & 24) | ((c ^ row) & 7);
      ldsm4(af[mf], sA_u + (unsigned)((row*32 + phys)*16));
    }
    unsigned bbase = tb + (unsigned)(q * 16384);
    #pragma unroll
    for (int p = 0; p < 2; p++){
      uint32_t r[4];
      ldsm4(r, bbase + boff[ss][p]);
      bv[0][2*p] = r[0]; bv[0][2*p+1] = r[1];
      bv[1][2*p] = r[2]; bv[1][2*p+1] = r[3];
    }
  };

  for (int i = 0; i < ntiles; i++){
    cpa_wait<1>();                 // B tile i arrived (tile i+1 may be pending)
    __syncthreads();               // visible to all; dump(i-1) visible too

    unsigned tb = sBu + (unsigned)(i & 1) * 65536u;
    uint32_t acc[2][4][2];         // fp16 accumulators: 4 halves per (mf,nf)
    #pragma unroll
    for (int mf = 0; mf < 2; mf++)
      #pragma unroll
      for (int nf = 0; nf < 4; nf++){ acc[mf][nf][0] = 0u; acc[mf][nf][1] = 0u; }

    // one uninterrupted 16-step mma burst, fragments double-buffered
    uint32_t afb[2][2][4], bvb[2][2][4];
    frag_load(0, afb[0], bvb[0], tb);
    #pragma unroll
    for (int step = 0; step < 16; step++){
      int cur = step & 1;
      if (step < 15) frag_load(step + 1, afb[cur ^ 1], bvb[cur ^ 1], tb);
      if ((step & 3) == 0 && i > 0) scan_chunk((t0 + i - 1)*BN, step >> 2);
      #pragma unroll
      for (int mf = 0; mf < 2; mf++)
        #pragma unroll
        for (int nf = 0; nf < 4; nf++)
          mma16816h(acc[mf][nf], afb[cur][mf], bvb[cur][0][nf], bvb[cur][1][nf]);
    }

    __syncthreads();               // all B-tile reads + all scans(i-1) done

    // prefetch tile i+2 into buffer (i&1)
    if (i + 2 < ntiles) load_B_tile(sBu, i & 1, (t0 + i + 2)*BN, t);
    cpa_commit();                  // commit even when empty: keeps group counting aligned

    // dump sims tile i (fp16, no conversion) into the single sims buffer
    int r0r = wr + (lane >> 2);
    int c0c = wc + 2*(lane & 3);
    #pragma unroll
    for (int mf = 0; mf < 2; mf++){
      #pragma unroll
      for (int nf = 0; nf < 4; nf++){
        int rr = r0r + 16*mf, cc = c0c + 8*nf;
        *(uint32_t*)(smem + SM_S + rr*SROW + cc*2)     = acc[mf][nf][0];
        *(uint32_t*)(smem + SM_S + (rr+8)*SROW + cc*2) = acc[mf][nf][1];
      }
    }
  }

  // epilogue: scan last tile
  __syncthreads();
  #pragma unroll
  for (int q = 0; q < 4; q++) scan_chunk((t0 + ntiles - 1)*BN, q);

  size_t base = (size_t)(m0 + srow) * NCAND + (size_t)y * (4*KP) + (size_t)squad * KP;
  #pragma unroll
  for (int i = 0; i < KP; i++){ g_cval[base + i] = tv[i]; g_cidx[base + i] = ti[i]; }
}

// ---------------- kernel 3: merge + exact rescore + softmax + scatter ----------------
__global__ void __launch_bounds__(128) merge_kernel(const float* __restrict__ mf,
                                                    const int* __restrict__ lab,
                                                    float* __restrict__ out){
  int row = blockIdx.x, t = threadIdx.x, lane = t & 31, w = t >> 5;
  __shared__ float cv[NCAND];
  __shared__ int   ci[NCAND];
  __shared__ float xs[DIM];
  __shared__ float accs[NCLS];
  __shared__ int   selIdx[CSEL];
  __shared__ float ex[CSEL];
  __shared__ float wgt[KSEL]; __shared__ int flab[KSEL];

  for (int j = t; j < NCAND; j += 128){
    cv[j] = g_cval[(size_t)row*NCAND + j];
    ci[j] = g_cidx[(size_t)row*NCAND + j];
  }
  for (int j = t; j < DIM; j += 128) xs[j] = g_xn[row*DIM + j];
  for (int c = t; c < NCLS; c += 128) accs[c] = 0.f;
  __syncthreads();

  if (w == 0){
    for (int it = 0; it < CSEL; it++){
      float bv = -INFINITY; int bp = 0;
      for (int j = lane; j < NCAND; j += 32){
        float c = cv[j];
        if (c > bv){ bv = c; bp = j; }
      }
      #pragma unroll
      for (int o = 16; o; o >>= 1){
        float ov = __shfl_xor_sync(0xffffffffu, bv, o);
        int   op = __shfl_xor_sync(0xffffffffu, bp, o);
        if (ov > bv || (ov == bv && op < bp)){ bv = ov; bp = op; }
      }
      if (lane == 0){ selIdx[it] = ci[bp]; cv[bp] = -INFINITY; }
      __syncwarp();
    }
  }
  __syncthreads();

  for (int rr = 0; rr < CSEL/4; rr++){
    int c = w + 4*rr;
    const float* fr = mf + (size_t)selIdx[c] * DIM;
    float s = 0.f;
    #pragma unroll
    for (int j = 0; j < 8; j++){ int k = lane + 32*j; s += fr[k] * xs[k]; }
    #pragma unroll
    for (int o = 16; o; o >>= 1) s += __shfl_down_sync(0xffffffffu, s, o);
    if (lane == 0) ex[c] = s;
  }
  __syncthreads();

  if (t == 0){
    uint64_t um = 0;
    float sval[KSEL]; int sfeat[KSEL];
    for (int it = 0; it < KSEL; it++){
      float bv = -INFINITY; int bc = 0;
      for (int c = 0; c < CSEL; c++){
        if (!((um >> c) & 1ull) && ex[c] > bv){ bv = ex[c]; bc = c; }
      }
      um |= 1ull << bc;
      sval[it] = bv; sfeat[it] = selIdx[bc];
    }
    float m = sval[0], sum = 0.f;
    for (int i = 0; i < KSEL; i++){ float e = expf((sval[i]-m)/TAUF); wgt[i] = e; sum += e; }
    float inv = 1.f / sum;
    for (int i = 0; i < KSEL; i++){ wgt[i] *= inv; flab[i] = lab[sfeat[i]]; }
    for (int i = 0; i < KSEL; i++) accs[flab[i]] += wgt[i];
  }
  __syncthreads();
  for (int c = t; c < NCLS; c += 128) out[(size_t)row*NCLS + c] = accs[c] * LSCALE;
}

// ---------------- dummy (profiling alignment: gemm at launch position 3) ----------------
__global__ void dummy_kernel(){}

// ---------------- launch ----------------
extern "C" void kernel_launch(void* const* d_in, const int* in_sizes, int n_in,
                              void* d_out, int out_size){
  const float* x    = (const float*)d_in[0];
  const float* mean = (const float*)d_in[1];
  const float* stdv = (const float*)d_in[2];
  const float* mf   = (const float*)d_in[3];
  const int*   lab  = (const int*)d_in[4];
  float* out = (float*)d_out;

  cudaFuncSetAttribute(gemm_topk_kernel, cudaFuncAttributeMaxDynamicSharedMemorySize, SM_TOTAL);

  setup_kernel<<<NQ, DIM>>>(x, mean, stdv, mf);   // pos 0
  dummy_kernel<<<1, 32>>>();                      // pos 1
  dummy_kernel<<<1, 32>>>();                      // pos 2
  gemm_topk_kernel<<<dim3(NQ/BM, NSTRIPE), NT, SM_TOTAL>>>();  // pos 3
  merge_kernel<<<NQ, 128>>>(mf, lab, out);        // pos 4
}